// round 12
// baseline (speedup 1.0000x reference)
#include <cuda_runtime.h>
#include <cstdint>
#include <cmath>

// Problem constants (fixed by the reference)
constexpr int B  = 4;
constexpr int C  = 32;
constexpr int GW = 64;               // W = L = H = 64
constexpr int LH = GW * GW;          // 4096
constexpr int V  = GW * GW * GW;     // 262144
constexpr int BV = B * V;            // 1,048,576 = 256 * 4096
constexpr int NMAX = 200000;
constexpr unsigned MIN_PTS = 10;
constexpr int SCAN_BLOCKS = 256;     // each scans 4096 counts (1024 thr x uint4)

// Static scratch (no allocations allowed). Accessed ONLY from device code.
// g_counts and g_scan_status rely on the zero-at-module-load invariant, which
// every launch restores (gather re-zeroes them after reading).
__device__ __align__(128) float g_csr[(size_t)B * NMAX * C]; // CSR-ordered attr lines
__device__ int      g_vox        [B * NMAX];        // flat voxel id (b*V+v) or -1
__device__ unsigned g_counts     [BV];              // per-voxel point counts
__device__ unsigned g_cursor     [BV];              // global excl. offsets / CSR cursor
__device__ unsigned g_scan_status[SCAN_BLOCKS];     // lookback: (value<<2)|state

// ---------------------------------------------------------------------------
// K1: voxelize + histogram. Match XLA: (p-0)/0.05 folded to p * 20.0f
// (f32-rounded reciprocal is exactly 20.0f), separate rn-mul / rn-add.
// ---------------------------------------------------------------------------
__device__ __forceinline__ int voxelize(float p) {
    return (int)floorf(__fadd_rn(__fmul_rn(p, 20.0f), 0.5f));
}

__global__ void voxelize_count_kernel(const float* __restrict__ coords, int N) {
    int n = blockIdx.x * blockDim.x + threadIdx.x;
    int b = blockIdx.y;
    if (n >= N) return;

    const float* cb = coords + (size_t)b * 3 * N;
    int x = voxelize(cb[n]);
    int y = voxelize(cb[(size_t)N + n]);
    int z = voxelize(cb[(size_t)2 * N + n]);

    int bv = -1;
    if ((unsigned)x < (unsigned)GW && (unsigned)y < (unsigned)GW &&
        (unsigned)z < (unsigned)GW) {
        bv = b * V + x * LH + y * GW + z;
        atomicAdd(&g_counts[bv], 1u);
    }
    g_vox[b * NMAX + n] = bv;
}

// ---------------------------------------------------------------------------
// Block-level exclusive scan helper (1024 threads, 32 warps).
// ---------------------------------------------------------------------------
__device__ __forceinline__ unsigned block_exclusive_scan(unsigned v, unsigned* total) {
    __shared__ unsigned wsum[32];
    int tid  = threadIdx.x;
    int lane = tid & 31, wid = tid >> 5;

    unsigned x = v;
    #pragma unroll
    for (int d = 1; d < 32; d <<= 1) {
        unsigned t = __shfl_up_sync(0xffffffffu, x, d);
        if (lane >= d) x += t;
    }
    if (lane == 31) wsum[wid] = x;
    __syncthreads();
    if (wid == 0) {
        unsigned s = wsum[lane];
        #pragma unroll
        for (int d = 1; d < 32; d <<= 1) {
            unsigned t = __shfl_up_sync(0xffffffffu, s, d);
            if (lane >= d) s += t;
        }
        wsum[lane] = s;                    // inclusive warp-total prefix
    }
    __syncthreads();
    unsigned wp = (wid > 0) ? wsum[wid - 1] : 0u;
    *total = wsum[31];
    return wp + x - v;                     // exclusive prefix
}

// ---------------------------------------------------------------------------
// K2: single-pass scan with decoupled lookback. Writes GLOBAL exclusive
// prefixes of g_counts straight into g_cursor (uint4 per thread).
// Status word: (value << 2) | state; state 1 = aggregate, 2 = inclusive
// prefix. Totals < 2^20 so the shift is safe. All 256 blocks are co-resident
// (2 blocks/SM x 148 SMs = 296 slots), so the spin cannot deadlock.
// ---------------------------------------------------------------------------
__global__ void scan_cursor_kernel() {
    __shared__ unsigned s_prefix;
    int tid = threadIdx.x;
    int blk = blockIdx.x;
    int i4  = blk * 1024 + tid;                      // uint4 index, BV/4 total

    uint4 c = reinterpret_cast<const uint4*>(g_counts)[i4];
    unsigned tsum = c.x + c.y + c.z + c.w;

    unsigned total;
    unsigned ex = block_exclusive_scan(tsum, &total);

    if (tid == 0) {
        if (blk == 0) {
            atomicExch(&g_scan_status[0], (total << 2) | 2u);
            s_prefix = 0u;
        } else {
            atomicExch(&g_scan_status[blk], (total << 2) | 1u);
            unsigned p = 0u;
            int i = blk - 1;
            while (true) {
                unsigned s = atomicAdd(&g_scan_status[i], 0u);  // gpu-scope read
                unsigned st = s & 3u;
                if (st == 0u) continue;                // not published yet
                p += s >> 2;
                if (st == 2u) break;                   // hit a full prefix
                --i;
            }
            atomicExch(&g_scan_status[blk], ((p + total) << 2) | 2u);
            s_prefix = p;
        }
    }
    __syncthreads();

    unsigned p = s_prefix;
    uint4 o;
    o.x = ex + p;
    o.y = o.x + c.x;
    o.z = o.y + c.y;
    o.w = o.z + c.z;
    reinterpret_cast<uint4*>(g_cursor)[i4] = o;
}

// ---------------------------------------------------------------------------
// K3: scatter attribute lines into CSR order. One thread per point.
// Reads attrs [B][C][N] coalesced across lanes (fixed c, consecutive n);
// writes one contiguous 128B line per point at its CSR slot.
// ---------------------------------------------------------------------------
__global__ void scatter_csr_kernel(const float* __restrict__ attrs, int N) {
    int n = blockIdx.x * blockDim.x + threadIdx.x;
    int b = blockIdx.y;
    if (n >= N) return;
    int bv = g_vox[b * NMAX + n];
    if (bv < 0) return;

    unsigned pos = atomicAdd(&g_cursor[bv], 1u);

    const float* ab = attrs + (size_t)b * C * N + n;
    float v[C];
    #pragma unroll
    for (int c = 0; c < C; c++) v[c] = ab[(size_t)c * N];   // coalesced

    float4* dst = reinterpret_cast<float4*>(g_csr + (size_t)pos * C);
    #pragma unroll
    for (int j = 0; j < C / 4; j++)
        dst[j] = make_float4(v[4*j], v[4*j+1], v[4*j+2], v[4*j+3]);
}

// ---------------------------------------------------------------------------
// K4: gather max per voxel (warp lanes = channels). Each warp owns 8 voxels
// INTERLEAVED (8 independent predicated line-loads per step -> MLP=8; outer
// trips = max of the 8 counts). Block = 64 voxels. Also restores the
// zero-invariant of g_counts (own range) and g_scan_status for next launch.
// After K3, g_cursor[bv] == end offset; start = end - count.
// ---------------------------------------------------------------------------
__global__ void gather_finalize_kernel(float* __restrict__ out,
                                       float* __restrict__ occ) {
    __shared__ float    tile[64][C + 1];
    __shared__ unsigned scnt[64], send[64];

    int b  = blockIdx.y;
    int v0 = blockIdx.x * 64;
    int tx = threadIdx.x, ty = threadIdx.y;          // (32, 8)
    int tid = ty * 32 + tx;                          // 0..255

    if (ty == 0) scnt[tx]      = g_counts[b * V + v0 + tx];
    if (ty == 1) scnt[32 + tx] = g_counts[b * V + v0 + 32 + tx];
    if (ty == 2) send[tx]      = g_cursor[b * V + v0 + tx];
    if (ty == 3) send[32 + tx] = g_cursor[b * V + v0 + 32 + tx];
    __syncthreads();

    // Restore zero-invariant for the next launch (after reads are latched).
    if (ty == 4) g_counts[b * V + v0 + tx]      = 0u;
    if (ty == 5) g_counts[b * V + v0 + 32 + tx] = 0u;
    if (blockIdx.x == 0 && b == 0) g_scan_status[tid] = 0u;

    unsigned cnt[8], start[8];
    float m[8];
    unsigned maxc = 0;
    #pragma unroll
    for (int k = 0; k < 8; k++) {
        int vl = ty + 8 * k;
        cnt[k]   = scnt[vl];
        start[k] = send[vl] - cnt[k];
        m[k]     = -INFINITY;
        maxc     = (cnt[k] > maxc) ? cnt[k] : maxc;
    }

    for (unsigned i = 0; i < maxc; i++) {
        #pragma unroll
        for (int k = 0; k < 8; k++) {
            if (i < cnt[k])                           // predicated, independent
                m[k] = fmaxf(m[k], g_csr[(size_t)(start[k] + i) * C + tx]);
        }
    }

    #pragma unroll
    for (int k = 0; k < 8; k++)
        tile[ty + 8 * k][tx] = (cnt[k] > 0u) ? m[k] : 0.0f;
    __syncthreads();

    float* ob = out + (size_t)b * C * V + v0;
    #pragma unroll
    for (int j = 0; j < 4; j++) {
        int c = ty + 8 * j;
        ob[(size_t)c * V + tx]      = tile[tx][c];        // coalesced over v
        ob[(size_t)c * V + 32 + tx] = tile[32 + tx][c];
    }
    if (ty == 6)
        occ[b * V + v0 + tx]      = (scnt[tx]      >= MIN_PTS) ? 1.0f : 0.0f;
    if (ty == 7)
        occ[b * V + v0 + 32 + tx] = (scnt[32 + tx] >= MIN_PTS) ? 1.0f : 0.0f;
}

// ---------------------------------------------------------------------------
// Launch: d_out = [voxeldata (B*C*V f32)][occupancy (B*V f32)]
// ---------------------------------------------------------------------------
extern "C" void kernel_launch(void* const* d_in, const int* in_sizes, int n_in,
                              void* d_out, int out_size) {
    const float* coords = (const float*)d_in[0];   // [B,3,N]
    const float* attrs  = (const float*)d_in[1];   // [B,C,N]
    int N = in_sizes[0] / (B * 3);                 // 200000

    float* voxeldata = (float*)d_out;
    float* occ       = (float*)d_out + (size_t)B * C * V;

    dim3 vg((N + 255) / 256, B);
    voxelize_count_kernel<<<vg, 256>>>(coords, N);

    scan_cursor_kernel<<<SCAN_BLOCKS, 1024>>>();

    scatter_csr_kernel<<<vg, 256>>>(attrs, N);

    dim3 fb(32, 8);
    dim3 fg(V / 64, B);
    gather_finalize_kernel<<<fg, fb>>>(voxeldata, occ);
}

// round 13
// speedup vs baseline: 1.1430x; 1.1430x over previous
#include <cuda_runtime.h>
#include <cstdint>
#include <cmath>

// Problem constants (fixed by the reference)
constexpr int B  = 4;
constexpr int C  = 32;
constexpr int GW = 64;               // W = L = H = 64
constexpr int LH = GW * GW;          // 4096
constexpr int V  = GW * GW * GW;     // 262144
constexpr int BV = B * V;            // 1,048,576 = 256 * 4096
constexpr int NMAX = 200000;
constexpr unsigned MIN_PTS = 10;
constexpr int SCAN_BLOCKS = 256;     // each scans 4096 counts (1024 thr x uint4)

// Static scratch (no allocations allowed). Accessed ONLY from device code.
// g_counts and g_scan_status rely on the zero-at-module-load invariant, which
// every launch restores (gather re-zeroes them after reading).
__device__ __align__(128) float g_csr[(size_t)B * NMAX * C]; // CSR-ordered attr lines
__device__ int      g_vox        [B * NMAX];        // flat voxel id (b*V+v) or -1
__device__ unsigned g_counts     [BV];              // per-voxel point counts
__device__ unsigned g_cursor     [BV];              // global excl. offsets / CSR cursor
__device__ unsigned g_scan_status[SCAN_BLOCKS];     // lookback: (value<<2)|state

// ---------------------------------------------------------------------------
// K1: voxelize + histogram. Match XLA: (p-0)/0.05 folded to p * 20.0f
// (f32-rounded reciprocal is exactly 20.0f), separate rn-mul / rn-add.
// ---------------------------------------------------------------------------
__device__ __forceinline__ int voxelize(float p) {
    return (int)floorf(__fadd_rn(__fmul_rn(p, 20.0f), 0.5f));
}

__global__ void voxelize_count_kernel(const float* __restrict__ coords, int N) {
    int n = blockIdx.x * blockDim.x + threadIdx.x;
    int b = blockIdx.y;
    if (n >= N) return;

    const float* cb = coords + (size_t)b * 3 * N;
    int x = voxelize(cb[n]);
    int y = voxelize(cb[(size_t)N + n]);
    int z = voxelize(cb[(size_t)2 * N + n]);

    int bv = -1;
    if ((unsigned)x < (unsigned)GW && (unsigned)y < (unsigned)GW &&
        (unsigned)z < (unsigned)GW) {
        bv = b * V + x * LH + y * GW + z;
        atomicAdd(&g_counts[bv], 1u);
    }
    g_vox[b * NMAX + n] = bv;
}

// ---------------------------------------------------------------------------
// Block-level exclusive scan helper (1024 threads, 32 warps).
// ---------------------------------------------------------------------------
__device__ __forceinline__ unsigned block_exclusive_scan(unsigned v, unsigned* total) {
    __shared__ unsigned wsum[32];
    int tid  = threadIdx.x;
    int lane = tid & 31, wid = tid >> 5;

    unsigned x = v;
    #pragma unroll
    for (int d = 1; d < 32; d <<= 1) {
        unsigned t = __shfl_up_sync(0xffffffffu, x, d);
        if (lane >= d) x += t;
    }
    if (lane == 31) wsum[wid] = x;
    __syncthreads();
    if (wid == 0) {
        unsigned s = wsum[lane];
        #pragma unroll
        for (int d = 1; d < 32; d <<= 1) {
            unsigned t = __shfl_up_sync(0xffffffffu, s, d);
            if (lane >= d) s += t;
        }
        wsum[lane] = s;                    // inclusive warp-total prefix
    }
    __syncthreads();
    unsigned wp = (wid > 0) ? wsum[wid - 1] : 0u;
    *total = wsum[31];
    return wp + x - v;                     // exclusive prefix
}

// ---------------------------------------------------------------------------
// K2: single-pass scan with decoupled lookback. Writes GLOBAL exclusive
// prefixes of g_counts straight into g_cursor (uint4 per thread).
// Status word: (value << 2) | state; state 1 = aggregate, 2 = inclusive
// prefix. Totals < 2^20 so the shift is safe. All 256 blocks are co-resident
// (2 blocks/SM x 148 SMs = 296 slots), so the spin cannot deadlock.
// ---------------------------------------------------------------------------
__global__ void scan_cursor_kernel() {
    __shared__ unsigned s_prefix;
    int tid = threadIdx.x;
    int blk = blockIdx.x;
    int i4  = blk * 1024 + tid;                      // uint4 index, BV/4 total

    uint4 c = reinterpret_cast<const uint4*>(g_counts)[i4];
    unsigned tsum = c.x + c.y + c.z + c.w;

    unsigned total;
    unsigned ex = block_exclusive_scan(tsum, &total);

    if (tid == 0) {
        if (blk == 0) {
            atomicExch(&g_scan_status[0], (total << 2) | 2u);
            s_prefix = 0u;
        } else {
            atomicExch(&g_scan_status[blk], (total << 2) | 1u);
            unsigned p = 0u;
            int i = blk - 1;
            while (true) {
                unsigned s = atomicAdd(&g_scan_status[i], 0u);  // gpu-scope read
                unsigned st = s & 3u;
                if (st == 0u) continue;                // not published yet
                p += s >> 2;
                if (st == 2u) break;                   // hit a full prefix
                --i;
            }
            atomicExch(&g_scan_status[blk], ((p + total) << 2) | 2u);
            s_prefix = p;
        }
    }
    __syncthreads();

    unsigned p = s_prefix;
    uint4 o;
    o.x = ex + p;
    o.y = o.x + c.x;
    o.z = o.y + c.y;
    o.w = o.z + c.z;
    reinterpret_cast<uint4*>(g_cursor)[i4] = o;
}

// ---------------------------------------------------------------------------
// K3: scatter attribute lines into CSR order. One thread per point.
// Reads attrs [B][C][N] coalesced across lanes (fixed c, consecutive n);
// writes one contiguous 128B line per point at its CSR slot.
// ---------------------------------------------------------------------------
__global__ void scatter_csr_kernel(const float* __restrict__ attrs, int N) {
    int n = blockIdx.x * blockDim.x + threadIdx.x;
    int b = blockIdx.y;
    if (n >= N) return;
    int bv = g_vox[b * NMAX + n];
    if (bv < 0) return;

    unsigned pos = atomicAdd(&g_cursor[bv], 1u);

    const float* ab = attrs + (size_t)b * C * N + n;
    float v[C];
    #pragma unroll
    for (int c = 0; c < C; c++) v[c] = ab[(size_t)c * N];   // coalesced

    float4* dst = reinterpret_cast<float4*>(g_csr + (size_t)pos * C);
    #pragma unroll
    for (int j = 0; j < C / 4; j++)
        dst[j] = make_float4(v[4*j], v[4*j+1], v[4*j+2], v[4*j+3]);
}

// ---------------------------------------------------------------------------
// K4: gather max per voxel (warp lanes = channels). Each warp owns 4 voxels
// INTERLEAVED (4 independent predicated line-loads per step -> MLP=4; outer
// trips = max of the 4 counts). Block = 32 voxels (the R10 shape: ~40 regs,
// high occupancy — the 8-wide variant regressed to 60 regs / 47% occ).
// Also restores the zero-invariant of g_counts (own range) and g_scan_status
// for the next launch. After K3, g_cursor[bv] == end; start = end - count.
// ---------------------------------------------------------------------------
__global__ void gather_finalize_kernel(float* __restrict__ out,
                                       float* __restrict__ occ) {
    __shared__ float    tile[32][C + 1];
    __shared__ unsigned scnt[32], send[32];

    int b  = blockIdx.y;
    int v0 = blockIdx.x * 32;
    int tx = threadIdx.x, ty = threadIdx.y;          // (32, 8)
    int tid = ty * 32 + tx;                          // 0..255

    if (ty == 0) scnt[tx] = g_counts[b * V + v0 + tx];
    if (ty == 1) send[tx] = g_cursor[b * V + v0 + tx];
    __syncthreads();

    // Restore zero-invariant for the next launch (after reads are latched).
    if (ty == 2) g_counts[b * V + v0 + tx] = 0u;
    if (blockIdx.x == 0 && b == 0) g_scan_status[tid & 255] = 0u;

    unsigned cnt[4], start[4];
    float m[4];
    unsigned maxc = 0;
    #pragma unroll
    for (int k = 0; k < 4; k++) {
        int vl = ty + 8 * k;
        cnt[k]   = scnt[vl];
        start[k] = send[vl] - cnt[k];
        m[k]     = -INFINITY;
        maxc     = (cnt[k] > maxc) ? cnt[k] : maxc;
    }

    for (unsigned i = 0; i < maxc; i++) {
        #pragma unroll
        for (int k = 0; k < 4; k++) {
            if (i < cnt[k])                           // predicated, independent
                m[k] = fmaxf(m[k], g_csr[(size_t)(start[k] + i) * C + tx]);
        }
    }

    #pragma unroll
    for (int k = 0; k < 4; k++)
        tile[ty + 8 * k][tx] = (cnt[k] > 0u) ? m[k] : 0.0f;
    __syncthreads();

    float* ob = out + (size_t)b * C * V + v0;
    #pragma unroll
    for (int j = 0; j < 4; j++) {
        int c = ty + 8 * j;
        ob[(size_t)c * V + tx] = tile[tx][c];        // coalesced over v
    }
    if (ty == 4)
        occ[b * V + v0 + tx] = (scnt[tx] >= MIN_PTS) ? 1.0f : 0.0f;
}

// ---------------------------------------------------------------------------
// Launch: d_out = [voxeldata (B*C*V f32)][occupancy (B*V f32)]
// ---------------------------------------------------------------------------
extern "C" void kernel_launch(void* const* d_in, const int* in_sizes, int n_in,
                              void* d_out, int out_size) {
    const float* coords = (const float*)d_in[0];   // [B,3,N]
    const float* attrs  = (const float*)d_in[1];   // [B,C,N]
    int N = in_sizes[0] / (B * 3);                 // 200000

    float* voxeldata = (float*)d_out;
    float* occ       = (float*)d_out + (size_t)B * C * V;

    dim3 vg((N + 255) / 256, B);
    voxelize_count_kernel<<<vg, 256>>>(coords, N);

    scan_cursor_kernel<<<SCAN_BLOCKS, 1024>>>();

    scatter_csr_kernel<<<vg, 256>>>(attrs, N);

    dim3 fb(32, 8);
    dim3 fg(V / 32, B);
    gather_finalize_kernel<<<fg, fb>>>(voxeldata, occ);
}